// round 3
// baseline (speedup 1.0000x reference)
#include <cuda_runtime.h>
#include <cuda_bf16.h>

#define N_NODES 50000
#define N_EDGES 800000
#define IN_DIM  128
#define HD      128   // N_HEAD * OUT_DIM
#define NHEAD   4
#define IN_E    16

#define SCAN_BS 512
#define NBLK    ((N_NODES + SCAN_BS - 1) / SCAN_BS)   // 98

// ---------------- scratch (__device__ globals; alloc-free rule) ----------------
__device__ float g_featn[(size_t)N_NODES * HD];   // projected node features [N,128]
__device__ float g_el[N_NODES * NHEAD];
__device__ float g_er[N_NODES * NHEAD];
__device__ float g_lg[(size_t)N_EDGES * NHEAD];   // logits, overwritten with exp in k_node pass2
__device__ int   g_cnt[N_NODES];                  // in-degree histogram
__device__ int   g_off[N_NODES + 1];              // CSR offsets (exclusive scan)
__device__ int   g_cur[N_NODES];                  // scatter cursors
__device__ int2  g_csr[N_EDGES];                  // {edge_id, src_node} sorted by dst
__device__ int   g_bsum[NBLK];
__device__ int   g_bpre[NBLK];

// ---------------- f32x2 packed-FMA helpers (sm_100+) ----------------
typedef unsigned long long ull;
__device__ __forceinline__ void ffma2(ull& d, ull a, ull b) {
    asm("fma.rn.f32x2 %0, %1, %2, %0;" : "+l"(d) : "l"(a), "l"(b));
}
__device__ __forceinline__ ull pack2(float v) {
    ull r; asm("mov.b64 %0, {%1, %1};" : "=l"(r) : "f"(v)); return r;
}

// ---------------- K1: node projection SGEMM (f32x2 packed) + g_cnt zero ----------------
// 256 threads; block tile 128 nodes x 128 outs; thread tile 8x8.
#define GSTR 132
__global__ void k_gemm(const float* __restrict__ x, const float* __restrict__ W) {
    extern __shared__ float sm[];
    float* Wsm = sm;                    // [k*132 + out]
    float* Xs  = sm + IN_DIM * GSTR;    // [k*132 + n_local]
    int tid = threadIdx.x;
    int base = blockIdx.x * 128;

    // fused: zero the in-degree histogram (grid covers >= N_NODES threads)
    int zi = blockIdx.x * 256 + tid;
    if (zi < N_NODES) g_cnt[zi] = 0;

    for (int i = tid; i < 128 * 128; i += 256) {
        int out = i >> 7, k = i & 127;
        Wsm[k * GSTR + out] = W[i];
    }
    for (int i = tid; i < 128 * 128; i += 256) {
        int n = i >> 7, k = i & 127;
        int gn = base + n;
        Xs[k * GSTR + n] = (gn < N_NODES) ? x[(size_t)gn * IN_DIM + k] : 0.0f;
    }
    __syncthreads();

    int ty = tid >> 4, tx = tid & 15;         // ty: 8 nodes, tx: 8 outs
    int n0 = ty * 8, c0 = tx * 8;
    ull acc[8][4];
    #pragma unroll
    for (int j = 0; j < 8; j++)
        #pragma unroll
        for (int p = 0; p < 4; p++) acc[j][p] = 0ull;

    #pragma unroll 4
    for (int k = 0; k < IN_DIM; k++) {
        const float* xr = Xs  + k * GSTR + n0;
        const float* wr = Wsm + k * GSTR + c0;
        ulonglong2 w0 = *(const ulonglong2*)(wr);
        ulonglong2 w1 = *(const ulonglong2*)(wr + 4);
        float4 xa = *(const float4*)(xr);
        float4 xb = *(const float4*)(xr + 4);
        float xv[8] = {xa.x, xa.y, xa.z, xa.w, xb.x, xb.y, xb.z, xb.w};
        #pragma unroll
        for (int j = 0; j < 8; j++) {
            ull px = pack2(xv[j]);
            ffma2(acc[j][0], px, w0.x);
            ffma2(acc[j][1], px, w0.y);
            ffma2(acc[j][2], px, w1.x);
            ffma2(acc[j][3], px, w1.y);
        }
    }
    #pragma unroll
    for (int j = 0; j < 8; j++) {
        int node = base + n0 + j;
        if (node < N_NODES) {
            ull* o = (ull*)(g_featn + (size_t)node * HD + c0);
            o[0] = acc[j][0]; o[1] = acc[j][1]; o[2] = acc[j][2]; o[3] = acc[j][3];
        }
    }
}

// ---------------- K2: per-node attention logits el/er ----------------
__global__ void k_attn(const float* __restrict__ al, const float* __restrict__ ar) {
    int w = (blockIdx.x * blockDim.x + threadIdx.x) >> 5;
    if (w >= N_NODES) return;
    int lane = threadIdx.x & 31;
    int c = lane * 4, h = lane >> 3;
    float4 f = *(const float4*)(g_featn + (size_t)w * HD + c);
    float4 a = *(const float4*)(al + c);
    float4 b = *(const float4*)(ar + c);
    float pl = f.x * a.x + f.y * a.y + f.z * a.z + f.w * a.w;
    float pr = f.x * b.x + f.y * b.y + f.z * b.z + f.w * b.w;
    #pragma unroll
    for (int o = 1; o < 8; o <<= 1) {
        pl += __shfl_xor_sync(0xffffffffu, pl, o);
        pr += __shfl_xor_sync(0xffffffffu, pr, o);
    }
    if ((lane & 7) == 0) {
        g_el[w * NHEAD + h] = pl;
        g_er[w * NHEAD + h] = pr;
    }
}

// ---------------- K3: edge logits + leaky relu + degree histogram ----------------
// 2 edges per thread (t and t + E/2) for doubled memory-level parallelism.
#define EHALF (N_EDGES / 2)
__global__ void k_logit(const float* __restrict__ fe, const int* __restrict__ src,
                        const int* __restrict__ dst, const float* __restrict__ ae) {
    __shared__ float aesm[NHEAD * IN_E];
    if (threadIdx.x < NHEAD * IN_E) aesm[threadIdx.x] = ae[threadIdx.x];
    __syncthreads();
    int t = blockIdx.x * blockDim.x + threadIdx.x;
    if (t >= EHALF) return;
    int e0 = t, e1 = t + EHALF;

    int s0 = src[e0], d0 = dst[e0];
    int s1 = src[e1], d1 = dst[e1];

    const float4* fr0 = (const float4*)(fe + (size_t)e0 * IN_E);
    const float4* fr1 = (const float4*)(fe + (size_t)e1 * IN_E);
    float4 fa0 = fr0[0], fa1 = fr0[1], fa2 = fr0[2], fa3 = fr0[3];
    float4 fb0 = fr1[0], fb1 = fr1[1], fb2 = fr1[2], fb3 = fr1[3];

    float4 el0 = *(const float4*)(g_el + s0 * NHEAD);
    float4 er0 = *(const float4*)(g_er + d0 * NHEAD);
    float4 el1 = *(const float4*)(g_el + s1 * NHEAD);
    float4 er1 = *(const float4*)(g_er + d1 * NHEAD);

    float els0[4] = {el0.x, el0.y, el0.z, el0.w};
    float ers0[4] = {er0.x, er0.y, er0.z, er0.w};
    float els1[4] = {el1.x, el1.y, el1.z, el1.w};
    float ers1[4] = {er1.x, er1.y, er1.z, er1.w};

    float lg0[4], lg1[4];
    #pragma unroll
    for (int h = 0; h < NHEAD; h++) {
        const float* a = aesm + h * IN_E;
        float ee0 = fa0.x*a[0]  + fa0.y*a[1]  + fa0.z*a[2]  + fa0.w*a[3]
                  + fa1.x*a[4]  + fa1.y*a[5]  + fa1.z*a[6]  + fa1.w*a[7]
                  + fa2.x*a[8]  + fa2.y*a[9]  + fa2.z*a[10] + fa2.w*a[11]
                  + fa3.x*a[12] + fa3.y*a[13] + fa3.z*a[14] + fa3.w*a[15];
        float ee1 = fb0.x*a[0]  + fb0.y*a[1]  + fb0.z*a[2]  + fb0.w*a[3]
                  + fb1.x*a[4]  + fb1.y*a[5]  + fb1.z*a[6]  + fb1.w*a[7]
                  + fb2.x*a[8]  + fb2.y*a[9]  + fb2.z*a[10] + fb2.w*a[11]
                  + fb3.x*a[12] + fb3.y*a[13] + fb3.z*a[14] + fb3.w*a[15];
        float v0 = els0[h] + ers0[h] + ee0;
        float v1 = els1[h] + ers1[h] + ee1;
        lg0[h] = v0 > 0.0f ? v0 : 0.2f * v0;
        lg1[h] = v1 > 0.0f ? v1 : 0.2f * v1;
    }
    ((float4*)g_lg)[e0] = make_float4(lg0[0], lg0[1], lg0[2], lg0[3]);
    ((float4*)g_lg)[e1] = make_float4(lg1[0], lg1[1], lg1[2], lg1[3]);
    atomicAdd(&g_cnt[d0], 1);
    atomicAdd(&g_cnt[d1], 1);
}

// ---------------- K4a/b/c: exclusive scan of degrees -> CSR offsets ----------------
__global__ void k_scan1() {
    __shared__ int s[SCAN_BS];
    int t = threadIdx.x;
    int i = blockIdx.x * SCAN_BS + t;
    int v = (i < N_NODES) ? g_cnt[i] : 0;
    s[t] = v; __syncthreads();
    for (int o = 1; o < SCAN_BS; o <<= 1) {
        int u = (t >= o) ? s[t - o] : 0;
        __syncthreads();
        s[t] += u;
        __syncthreads();
    }
    if (i < N_NODES) g_off[i] = s[t] - v;              // exclusive
    if (t == SCAN_BS - 1) g_bsum[blockIdx.x] = s[t];
}
__global__ void k_scan2() {
    __shared__ int s[128];
    int t = threadIdx.x;
    int v = (t < NBLK) ? g_bsum[t] : 0;
    s[t] = v; __syncthreads();
    for (int o = 1; o < 128; o <<= 1) {
        int u = (t >= o) ? s[t - o] : 0;
        __syncthreads();
        s[t] += u;
        __syncthreads();
    }
    if (t < NBLK) g_bpre[t] = s[t] - v;                // exclusive
}
__global__ void k_scan3() {
    int i = blockIdx.x * SCAN_BS + threadIdx.x;
    if (i == 0) g_off[N_NODES] = N_EDGES;
    if (i < N_NODES) {
        int v = g_off[i] + g_bpre[blockIdx.x];
        g_off[i] = v;
        g_cur[i] = v;
    }
}

// ---------------- K5: scatter edges into CSR (sorted by dst) ----------------
__global__ void k_scatter(const int* __restrict__ src, const int* __restrict__ dst) {
    int e = blockIdx.x * blockDim.x + threadIdx.x;
    if (e >= N_EDGES) return;
    int d = dst[e];
    int pos = atomicAdd(&g_cur[d], 1);
    g_csr[pos] = make_int2(e, src[e]);
}

// ---------------- K6: per-dst-node softmax + weighted aggregate ----------------
// warp per node; lane handles 4 output cols; no output atomics; exp computed ONCE.
__global__ void k_node(float* __restrict__ out) {
    int w = (blockIdx.x * blockDim.x + threadIdx.x) >> 5;
    if (w >= N_NODES) return;
    int lane = threadIdx.x & 31;
    int c = lane * 4, h = lane >> 3;
    float* orow = out + (size_t)w * HD + c;

    int beg = g_off[w], end = g_off[w + 1];
    if (beg == end) {                                   // zero-degree node
        *(float4*)orow = make_float4(0.f, 0.f, 0.f, 0.f);
        return;
    }
    const float NEG = -3.4e38f;
    // pass 1: per-head max over in-edges
    float4 mx = make_float4(NEG, NEG, NEG, NEG);
    for (int p = beg + lane; p < end; p += 32) {
        float4 lg = ((const float4*)g_lg)[g_csr[p].x];
        mx.x = fmaxf(mx.x, lg.x); mx.y = fmaxf(mx.y, lg.y);
        mx.z = fmaxf(mx.z, lg.z); mx.w = fmaxf(mx.w, lg.w);
    }
    #pragma unroll
    for (int o = 16; o; o >>= 1) {
        mx.x = fmaxf(mx.x, __shfl_xor_sync(0xffffffffu, mx.x, o));
        mx.y = fmaxf(mx.y, __shfl_xor_sync(0xffffffffu, mx.y, o));
        mx.z = fmaxf(mx.z, __shfl_xor_sync(0xffffffffu, mx.z, o));
        mx.w = fmaxf(mx.w, __shfl_xor_sync(0xffffffffu, mx.w, o));
    }
    // pass 2: exp once, write back in place (warp owns these edges exclusively), sum
    float4 sm = make_float4(0.f, 0.f, 0.f, 0.f);
    for (int p = beg + lane; p < end; p += 32) {
        int e = g_csr[p].x;
        float4 lg = ((const float4*)g_lg)[e];
        float4 ex = make_float4(__expf(lg.x - mx.x), __expf(lg.y - mx.y),
                                __expf(lg.z - mx.z), __expf(lg.w - mx.w));
        ((float4*)g_lg)[e] = ex;
        sm.x += ex.x; sm.y += ex.y; sm.z += ex.z; sm.w += ex.w;
    }
    #pragma unroll
    for (int o = 16; o; o >>= 1) {
        sm.x += __shfl_xor_sync(0xffffffffu, sm.x, o);
        sm.y += __shfl_xor_sync(0xffffffffu, sm.y, o);
        sm.z += __shfl_xor_sync(0xffffffffu, sm.z, o);
        sm.w += __shfl_xor_sync(0xffffffffu, sm.w, o);
    }
    float sh = (h < 2) ? (h == 0 ? sm.x : sm.y) : (h == 2 ? sm.z : sm.w);
    float inv = 1.0f / sh;
    // pass 3: weighted gather-accumulate (no exp — load stored value)
    float4 acc = make_float4(0.f, 0.f, 0.f, 0.f);
    for (int p = beg; p < end; p++) {
        int2 es = g_csr[p];                              // uniform across warp
        float a = g_lg[(size_t)es.x * NHEAD + h] * inv;
        float4 f = *(const float4*)(g_featn + (size_t)es.y * HD + c);
        acc.x += f.x * a; acc.y += f.y * a; acc.z += f.z * a; acc.w += f.w * a;
    }
    *(float4*)orow = acc;
}

// ---------------- launch ----------------
extern "C" void kernel_launch(void* const* d_in, const int* in_sizes, int n_in,
                              void* d_out, int out_size) {
    const float* feats_node = (const float*)d_in[0];
    const float* feats_edge = (const float*)d_in[1];
    const int*   src        = (const int*)d_in[2];
    const int*   dst        = (const int*)d_in[3];
    const float* W_node     = (const float*)d_in[4];
    const float* attn_l     = (const float*)d_in[5];
    const float* attn_r     = (const float*)d_in[6];
    const float* attn_e     = (const float*)d_in[7];
    float* out = (float*)d_out;

    int gsm = 2 * IN_DIM * GSTR * sizeof(float);        // 135168 B
    static int configured = 0;
    if (!configured) {
        cudaFuncSetAttribute(k_gemm, cudaFuncAttributeMaxDynamicSharedMemorySize, gsm);
        configured = 1;
    }

    k_gemm<<<(N_NODES + 127) / 128, 256, gsm>>>(feats_node, W_node);
    k_attn<<<(N_NODES * 32 + 255) / 256, 256>>>(attn_l, attn_r);
    k_logit<<<(EHALF + 255) / 256, 256>>>(feats_edge, src, dst, attn_e);
    k_scan1<<<NBLK, SCAN_BS>>>();
    k_scan2<<<1, 128>>>();
    k_scan3<<<NBLK, SCAN_BS>>>();
    k_scatter<<<(N_EDGES + 255) / 256, 256>>>(src, dst);
    k_node<<<(N_NODES * 32 + 255) / 256, 256>>>(out);
}

// round 4
// speedup vs baseline: 1.0552x; 1.0552x over previous
#include <cuda_runtime.h>
#include <cuda_bf16.h>

#define N_NODES 50000
#define N_EDGES 800000
#define IN_DIM  128
#define HD      128   // N_HEAD * OUT_DIM
#define NHEAD   4
#define IN_E    16

#define SCAN_BS 512
#define NBLK    ((N_NODES + SCAN_BS - 1) / SCAN_BS)   // 98

// ---------------- scratch (__device__ globals; alloc-free rule) ----------------
__device__ float g_featn[(size_t)N_NODES * HD];   // projected node features [N,128]
__device__ float g_el[N_NODES * NHEAD];
__device__ float g_er[N_NODES * NHEAD];
__device__ float g_lgs[(size_t)N_EDGES * NHEAD];  // leaky-relu logits in CSR (dst-sorted) order
__device__ int   g_srcs[N_EDGES];                 // src node per CSR slot
__device__ int   g_cnt[N_NODES];                  // in-degree histogram
__device__ int   g_off[N_NODES + 1];              // CSR offsets (exclusive scan)
__device__ int   g_cur[N_NODES];                  // scatter cursors
__device__ int   g_bsum[NBLK];
__device__ int   g_bpre[NBLK];

// ---------------- f32x2 packed-FMA helpers (sm_100+) ----------------
typedef unsigned long long ull;
__device__ __forceinline__ void ffma2(ull& d, ull a, ull b) {
    asm("fma.rn.f32x2 %0, %1, %2, %0;" : "+l"(d) : "l"(a), "l"(b));
}
__device__ __forceinline__ ull pack2(float v) {
    ull r; asm("mov.b64 %0, {%1, %1};" : "=l"(r) : "f"(v)); return r;
}

// ---------------- K1: node projection SGEMM (f32x2 packed) + g_cnt zero ----------------
#define GSTR 132
__global__ void k_gemm(const float* __restrict__ x, const float* __restrict__ W) {
    extern __shared__ float sm[];
    float* Wsm = sm;                    // [k*132 + out]
    float* Xs  = sm + IN_DIM * GSTR;    // [k*132 + n_local]
    int tid = threadIdx.x;
    int base = blockIdx.x * 128;

    // fused: zero the in-degree histogram
    int zi = blockIdx.x * 256 + tid;
    if (zi < N_NODES) g_cnt[zi] = 0;

    for (int i = tid; i < 128 * 128; i += 256) {
        int out = i >> 7, k = i & 127;
        Wsm[k * GSTR + out] = W[i];
    }
    for (int i = tid; i < 128 * 128; i += 256) {
        int n = i >> 7, k = i & 127;
        int gn = base + n;
        Xs[k * GSTR + n] = (gn < N_NODES) ? x[(size_t)gn * IN_DIM + k] : 0.0f;
    }
    __syncthreads();

    int ty = tid >> 4, tx = tid & 15;         // ty: 8 nodes, tx: 8 outs
    int n0 = ty * 8, c0 = tx * 8;
    ull acc[8][4];
    #pragma unroll
    for (int j = 0; j < 8; j++)
        #pragma unroll
        for (int p = 0; p < 4; p++) acc[j][p] = 0ull;

    #pragma unroll 4
    for (int k = 0; k < IN_DIM; k++) {
        const float* xr = Xs  + k * GSTR + n0;
        const float* wr = Wsm + k * GSTR + c0;
        ulonglong2 w0 = *(const ulonglong2*)(wr);
        ulonglong2 w1 = *(const ulonglong2*)(wr + 4);
        float4 xa = *(const float4*)(xr);
        float4 xb = *(const float4*)(xr + 4);
        float xv[8] = {xa.x, xa.y, xa.z, xa.w, xb.x, xb.y, xb.z, xb.w};
        #pragma unroll
        for (int j = 0; j < 8; j++) {
            ull px = pack2(xv[j]);
            ffma2(acc[j][0], px, w0.x);
            ffma2(acc[j][1], px, w0.y);
            ffma2(acc[j][2], px, w1.x);
            ffma2(acc[j][3], px, w1.y);
        }
    }
    #pragma unroll
    for (int j = 0; j < 8; j++) {
        int node = base + n0 + j;
        if (node < N_NODES) {
            ull* o = (ull*)(g_featn + (size_t)node * HD + c0);
            o[0] = acc[j][0]; o[1] = acc[j][1]; o[2] = acc[j][2]; o[3] = acc[j][3];
        }
    }
}

// ---------------- K2: per-node el/er + fused in-degree histogram ----------------
__global__ void k_attn(const float* __restrict__ al, const float* __restrict__ ar,
                       const int* __restrict__ dst) {
    int gid = blockIdx.x * blockDim.x + threadIdx.x;
    // fused histogram: first N_EDGES threads each count one edge
    if (gid < N_EDGES) atomicAdd(&g_cnt[dst[gid]], 1);

    int w = gid >> 5;
    if (w >= N_NODES) return;
    int lane = threadIdx.x & 31;
    int c = lane * 4, h = lane >> 3;
    float4 f = *(const float4*)(g_featn + (size_t)w * HD + c);
    float4 a = *(const float4*)(al + c);
    float4 b = *(const float4*)(ar + c);
    float pl = f.x * a.x + f.y * a.y + f.z * a.z + f.w * a.w;
    float pr = f.x * b.x + f.y * b.y + f.z * b.z + f.w * b.w;
    #pragma unroll
    for (int o = 1; o < 8; o <<= 1) {
        pl += __shfl_xor_sync(0xffffffffu, pl, o);
        pr += __shfl_xor_sync(0xffffffffu, pr, o);
    }
    if ((lane & 7) == 0) {
        g_el[w * NHEAD + h] = pl;
        g_er[w * NHEAD + h] = pr;
    }
}

// ---------------- K3a/b/c: exclusive scan of degrees -> CSR offsets ----------------
__global__ void k_scan1() {
    __shared__ int s[SCAN_BS];
    int t = threadIdx.x;
    int i = blockIdx.x * SCAN_BS + t;
    int v = (i < N_NODES) ? g_cnt[i] : 0;
    s[t] = v; __syncthreads();
    for (int o = 1; o < SCAN_BS; o <<= 1) {
        int u = (t >= o) ? s[t - o] : 0;
        __syncthreads();
        s[t] += u;
        __syncthreads();
    }
    if (i < N_NODES) g_off[i] = s[t] - v;              // exclusive
    if (t == SCAN_BS - 1) g_bsum[blockIdx.x] = s[t];
}
__global__ void k_scan2() {
    __shared__ int s[128];
    int t = threadIdx.x;
    int v = (t < NBLK) ? g_bsum[t] : 0;
    s[t] = v; __syncthreads();
    for (int o = 1; o < 128; o <<= 1) {
        int u = (t >= o) ? s[t - o] : 0;
        __syncthreads();
        s[t] += u;
        __syncthreads();
    }
    if (t < NBLK) g_bpre[t] = s[t] - v;                // exclusive
}
__global__ void k_scan3() {
    int i = blockIdx.x * SCAN_BS + threadIdx.x;
    if (i == 0) g_off[N_NODES] = N_EDGES;
    if (i < N_NODES) {
        int v = g_off[i] + g_bpre[blockIdx.x];
        g_off[i] = v;
        g_cur[i] = v;
    }
}

// ---------------- K4: edge logits + leaky relu, written directly in CSR order ----------------
__global__ void k_logit(const float* __restrict__ fe, const int* __restrict__ src,
                        const int* __restrict__ dst, const float* __restrict__ ae) {
    __shared__ float aesm[NHEAD * IN_E];
    if (threadIdx.x < NHEAD * IN_E) aesm[threadIdx.x] = ae[threadIdx.x];
    __syncthreads();
    int e = blockIdx.x * blockDim.x + threadIdx.x;
    if (e >= N_EDGES) return;
    int s = src[e], d = dst[e];

    const float4* fr = (const float4*)(fe + (size_t)e * IN_E);
    float4 f0 = fr[0], f1 = fr[1], f2 = fr[2], f3 = fr[3];
    float4 elv = *(const float4*)(g_el + s * NHEAD);
    float4 erv = *(const float4*)(g_er + d * NHEAD);
    float els[4] = {elv.x, elv.y, elv.z, elv.w};
    float ers[4] = {erv.x, erv.y, erv.z, erv.w};

    float lg[4];
    #pragma unroll
    for (int h = 0; h < NHEAD; h++) {
        const float* a = aesm + h * IN_E;
        float ee = f0.x*a[0]  + f0.y*a[1]  + f0.z*a[2]  + f0.w*a[3]
                 + f1.x*a[4]  + f1.y*a[5]  + f1.z*a[6]  + f1.w*a[7]
                 + f2.x*a[8]  + f2.y*a[9]  + f2.z*a[10] + f2.w*a[11]
                 + f3.x*a[12] + f3.y*a[13] + f3.z*a[14] + f3.w*a[15];
        float v = els[h] + ers[h] + ee;
        lg[h] = v > 0.0f ? v : 0.2f * v;                // leaky relu 0.2
    }
    int pos = atomicAdd(&g_cur[d], 1);                  // CSR slot
    ((float4*)g_lgs)[pos] = make_float4(lg[0], lg[1], lg[2], lg[3]);
    g_srcs[pos] = s;
}

// ---------------- K5: per-dst-node softmax + weighted aggregate ----------------
// warp per node; lane handles 4 output cols. Max pass (coalesced) + single merged
// accumulate pass: sum-of-exp and sum-of-exp*feat in one loop, normalize at end.
__global__ void k_node(float* __restrict__ out) {
    int w = (blockIdx.x * blockDim.x + threadIdx.x) >> 5;
    if (w >= N_NODES) return;
    int lane = threadIdx.x & 31;
    int c = lane * 4, h = lane >> 3;
    float* orow = out + (size_t)w * HD + c;

    int beg = g_off[w], end = g_off[w + 1];
    if (beg == end) {                                   // zero-degree node
        *(float4*)orow = make_float4(0.f, 0.f, 0.f, 0.f);
        return;
    }
    const float NEG = -3.4e38f;
    // pass 1: per-head max (coalesced sequential float4 loads)
    float4 mx = make_float4(NEG, NEG, NEG, NEG);
    for (int p = beg + lane; p < end; p += 32) {
        float4 lg = ((const float4*)g_lgs)[p];
        mx.x = fmaxf(mx.x, lg.x); mx.y = fmaxf(mx.y, lg.y);
        mx.z = fmaxf(mx.z, lg.z); mx.w = fmaxf(mx.w, lg.w);
    }
    #pragma unroll
    for (int o = 16; o; o >>= 1) {
        mx.x = fmaxf(mx.x, __shfl_xor_sync(0xffffffffu, mx.x, o));
        mx.y = fmaxf(mx.y, __shfl_xor_sync(0xffffffffu, mx.y, o));
        mx.z = fmaxf(mx.z, __shfl_xor_sync(0xffffffffu, mx.z, o));
        mx.w = fmaxf(mx.w, __shfl_xor_sync(0xffffffffu, mx.w, o));
    }
    float mh = (h == 0) ? mx.x : (h == 1) ? mx.y : (h == 2) ? mx.z : mx.w;

    // pass 2 (merged): sum of exp (per-lane; identical within head group) and
    // sum of exp * feat. src ids preloaded 32 at a time and shfl-broadcast.
    float sh = 0.0f;
    float4 acc = make_float4(0.f, 0.f, 0.f, 0.f);
    int p0 = beg;
    for (; p0 + 32 <= end; p0 += 32) {
        int sv = g_srcs[p0 + lane];
        #pragma unroll 4
        for (int j = 0; j < 32; j++) {
            int sn = __shfl_sync(0xffffffffu, sv, j);
            float lgv = g_lgs[(size_t)(p0 + j) * NHEAD + h];
            float a = __expf(lgv - mh);
            sh += a;
            float4 f = *(const float4*)(g_featn + (size_t)sn * HD + c);
            acc.x += a * f.x; acc.y += a * f.y; acc.z += a * f.z; acc.w += a * f.w;
        }
    }
    if (p0 < end) {
        int rem = end - p0;
        int sv = (lane < rem) ? g_srcs[p0 + lane] : 0;
        for (int j = 0; j < rem; j++) {
            int sn = __shfl_sync(0xffffffffu, sv, j);
            float lgv = g_lgs[(size_t)(p0 + j) * NHEAD + h];
            float a = __expf(lgv - mh);
            sh += a;
            float4 f = *(const float4*)(g_featn + (size_t)sn * HD + c);
            acc.x += a * f.x; acc.y += a * f.y; acc.z += a * f.z; acc.w += a * f.w;
        }
    }
    float inv = 1.0f / sh;
    acc.x *= inv; acc.y *= inv; acc.z *= inv; acc.w *= inv;
    *(float4*)orow = acc;
}

// ---------------- launch ----------------
extern "C" void kernel_launch(void* const* d_in, const int* in_sizes, int n_in,
                              void* d_out, int out_size) {
    const float* feats_node = (const float*)d_in[0];
    const float* feats_edge = (const float*)d_in[1];
    const int*   src        = (const int*)d_in[2];
    const int*   dst        = (const int*)d_in[3];
    const float* W_node     = (const float*)d_in[4];
    const float* attn_l     = (const float*)d_in[5];
    const float* attn_r     = (const float*)d_in[6];
    const float* attn_e     = (const float*)d_in[7];
    float* out = (float*)d_out;

    int gsm = 2 * IN_DIM * GSTR * sizeof(float);        // 135168 B
    static int configured = 0;
    if (!configured) {
        cudaFuncSetAttribute(k_gemm, cudaFuncAttributeMaxDynamicSharedMemorySize, gsm);
        configured = 1;
    }

    k_gemm<<<(N_NODES + 127) / 128, 256, gsm>>>(feats_node, W_node);
    k_attn<<<(N_NODES * 32 + 255) / 256, 256>>>(attn_l, attn_r, dst);
    k_scan1<<<NBLK, SCAN_BS>>>();
    k_scan2<<<1, 128>>>();
    k_scan3<<<NBLK, SCAN_BS>>>();
    k_logit<<<(N_EDGES + 255) / 256, 256>>>(feats_edge, src, dst, attn_e);
    k_node<<<(N_NODES * 32 + 255) / 256, 256>>>(out);
}